// round 16
// baseline (speedup 1.0000x reference)
#include <cuda_runtime.h>
#include <cuda_fp16.h>
#include <cstdint>

#define IN_DIM   256
#define OUT_DIM  64
#define HCOLS    192   // [hp | lp | i]
#define MAX_NODES 100000
#define MAX_EDGES 3300000

// ---------------- scratch (device globals: no allocations allowed) ----------
__device__ float   g_hall[(size_t)MAX_NODES * HCOLS];  // fp32 h (all paths)
__device__ __half2 g_hlp [(size_t)MAX_NODES * 64];     // fp16 mirror cols 0..127; pre-scaled by isq[src]
__device__ __half  g_xh  [(size_t)MAX_NODES * IN_DIM]; // fp16 mirror of x
__device__ __half  g_Wth [HCOLS * IN_DIM];             // fp16 W, TRANSPOSED: [n][k]
__device__ int     g_deg [MAX_NODES];
__device__ int     g_cur [MAX_NODES];
__device__ int     g_rowp[MAX_NODES + 1];
__device__ int     g_adj [MAX_EDGES];
__device__ float   g_isq [MAX_NODES];
__device__ float   g_inv [MAX_NODES];
__device__ float   g_ball[HCOLS];
__device__ int     g_is64;
__device__ int     g_bsum[128];

// ---------------- edge dtype detector (1 warp) -------------------------------
__global__ void k_detect(const void* __restrict__ ei, int E, int n) {
    const long long* p = (const long long*)ei;
    int lane = threadIdx.x;
    int idx = lane < E ? lane : (E > 0 ? E - 1 : 0);
    long long v = (E > 0) ? p[idx] : -1;
    bool good = (v >= 0 && v < (long long)n);
    unsigned all = __all_sync(0xFFFFFFFFu, good);
    if (lane == 0) g_is64 = all ? 1 : 0;
}

__device__ __forceinline__ int edge_at(const void* ei, size_t idx) {
    if (g_is64) return (int)((const long long*)ei)[idx];
    return ((const int*)ei)[idx];
}

// ---------------- x -> fp16 mirror -------------------------------------------
__global__ void k_xh(const float* __restrict__ x, int total4) {
    int t = blockIdx.x * blockDim.x + threadIdx.x;
    if (t >= total4) return;
    float4 v = reinterpret_cast<const float4*>(x)[t];
    __half2 h0 = __float22half2_rn(make_float2(v.x, v.y));
    __half2 h1 = __float22half2_rn(make_float2(v.z, v.w));
    uint2 o;
    o.x = *reinterpret_cast<uint32_t*>(&h0);
    o.y = *reinterpret_cast<uint32_t*>(&h1);
    reinterpret_cast<uint2*>(g_xh)[t] = o;
}

// ---------------- zero deg + cursors -----------------------------------------
__global__ void k_zero(int n) {
    int i = blockIdx.x * blockDim.x + threadIdx.x;
    if (i < n) { g_deg[i] = 0; g_cur[i] = 0; }
}

// ---------------- pack weights: fp16, transposed to [n][k] -------------------
__global__ void k_prep_w(const float* __restrict__ Whp, const float* __restrict__ bhp,
                         const float* __restrict__ Wlp, const float* __restrict__ blp,
                         const float* __restrict__ Wi,  const float* __restrict__ bi) {
    int idx = blockIdx.x * blockDim.x + threadIdx.x;
    if (idx < IN_DIM * HCOLS) {
        int k = idx / HCOLS, j = idx % HCOLS;
        float v;
        if      (j < 64)  v = Whp[k * 64 + j];
        else if (j < 128) v = Wlp[k * 64 + (j - 64)];
        else              v = Wi [k * 64 + (j - 128)];
        g_Wth[(size_t)j * IN_DIM + k] = __float2half_rn(v);
    }
    if (idx < HCOLS) {
        g_ball[idx] = (idx < 64) ? bhp[idx] : (idx < 128 ? blp[idx - 64] : bi[idx - 128]);
    }
}

// ---------------- degree count -----------------------------------------------
__global__ void k_deg(const void* __restrict__ ei, int E, int n) {
    int e = blockIdx.x * blockDim.x + threadIdx.x;
    if (e < E) {
        int dst = edge_at(ei, (size_t)E + e);
        if ((unsigned)dst < (unsigned)n) atomicAdd(&g_deg[dst], 1);
    }
}

// ---------------- multi-block scan: deg -> row_ptr ---------------------------
__global__ void __launch_bounds__(1024) k_scan1(int n) {
    __shared__ int sh[1024];
    int i = blockIdx.x * 1024 + threadIdx.x;
    sh[threadIdx.x] = (i < n) ? g_deg[i] : 0;
    __syncthreads();
#pragma unroll
    for (int off = 1; off < 1024; off <<= 1) {
        int t = (threadIdx.x >= off) ? sh[threadIdx.x - off] : 0;
        __syncthreads();
        sh[threadIdx.x] += t;
        __syncthreads();
    }
    if (i < n) g_rowp[i + 1] = sh[threadIdx.x];
    if (threadIdx.x == 1023) g_bsum[blockIdx.x] = sh[1023];
}
__global__ void __launch_bounds__(128) k_scan2(int nb) {
    __shared__ int sh[128];
    sh[threadIdx.x] = (threadIdx.x < nb) ? g_bsum[threadIdx.x] : 0;
    __syncthreads();
#pragma unroll
    for (int off = 1; off < 128; off <<= 1) {
        int t = (threadIdx.x >= off) ? sh[threadIdx.x - off] : 0;
        __syncthreads();
        sh[threadIdx.x] += t;
        __syncthreads();
    }
    g_bsum[threadIdx.x] = sh[threadIdx.x];
}
// scan3 + degfin fused
__global__ void k_scan3(int n) {
    int i = blockIdx.x * blockDim.x + threadIdx.x;
    if (i < n) {
        int b = i >> 10;
        if (b > 0) g_rowp[i + 1] += g_bsum[b - 1];
        float d = (float)g_deg[i] + 1.0f;
        g_isq[i] = rsqrtf(d);
        g_inv[i] = 1.0f / d;
    }
    if (i == 0) g_rowp[0] = 0;
}

// ---------------- scatter edges into CSR -------------------------------------
__global__ void k_scatter(const void* __restrict__ ei, int E, int n) {
    int e = blockIdx.x * blockDim.x + threadIdx.x;
    if (e < E) {
        int src = edge_at(ei, (size_t)e);
        int dst = edge_at(ei, (size_t)E + e);
        if ((unsigned)src < (unsigned)n && (unsigned)dst < (unsigned)n) {
            int pos = g_rowp[dst] + atomicAdd(&g_cur[dst], 1);
            if ((unsigned)pos < (unsigned)MAX_EDGES) g_adj[pos] = src;
        }
    }
}

// ---------------- prescale: g_hlp[i] *= isq[i] (row-wise) --------------------
__global__ void k_prescale(int n) {
    int t = blockIdx.x * blockDim.x + threadIdx.x;
    int total = n * 32;
    if (t >= total) return;
    int node = t >> 5;
    float s = g_isq[node];
    uint2 raw = *reinterpret_cast<const uint2*>(g_hlp + (size_t)t * 2);
    float2 f0 = __half22float2(*reinterpret_cast<__half2*>(&raw.x));
    float2 f1 = __half22float2(*reinterpret_cast<__half2*>(&raw.y));
    f0.x *= s; f0.y *= s; f1.x *= s; f1.y *= s;
    __half2 h0 = __float22half2_rn(f0), h1 = __float22half2_rn(f1);
    uint2 o; o.x = *reinterpret_cast<uint32_t*>(&h0); o.y = *reinterpret_cast<uint32_t*>(&h1);
    *reinterpret_cast<uint2*>(g_hlp + (size_t)t * 2) = o;
}

// ---------------- fp16 GEMM, cp.async double-buffered (R13-verified) ---------
// BM=128, BN=192, BK=32; 512 thr = 16 warps (4x4); warp tile 32x48.
__device__ __forceinline__ void cp16(void* smem, const void* gmem) {
    uint32_t s = (uint32_t)__cvta_generic_to_shared(smem);
    asm volatile("cp.async.cg.shared.global [%0], [%1], 16;" :: "r"(s), "l"(gmem));
}

#define AS_STRIDE 40
#define AS_ELEMS (128 * AS_STRIDE)
#define BS_ELEMS (HCOLS * AS_STRIDE)
#define GEMM_SMEM ((2 * AS_ELEMS + 2 * BS_ELEMS) * 2)   // 51200 bytes

__global__ void __launch_bounds__(512) k_gemm(int M) {
    extern __shared__ __half hsmem[];
    __half* As[2] = { hsmem, hsmem + AS_ELEMS };
    __half* Bs[2] = { hsmem + 2 * AS_ELEMS, hsmem + 2 * AS_ELEMS + BS_ELEMS };

    const int tid  = threadIdx.x;
    const int wid  = tid >> 5;
    const int lane = tid & 31;
    const int m0 = blockIdx.x * 128;
    const int wm = (wid >> 2) * 32;
    const int wn = (wid & 3) * 48;
    const int grp = lane >> 2;
    const int tig = lane & 3;

    const int arow = tid >> 2, achk = (tid & 3) * 8;
    auto load_stage = [&](int buf, int k0) {
        {
            int m = m0 + arow;
            int ms = m < M ? m : M - 1;
            cp16(&As[buf][arow * AS_STRIDE + achk], g_xh + (size_t)ms * IN_DIM + k0 + achk);
        }
#pragma unroll
        for (int r = 0; r < 2; r++) {
            int f = tid + r * 512;
            if (f < HCOLS * 4) {
                int row = f >> 2, chk = (f & 3) * 8;
                cp16(&Bs[buf][row * AS_STRIDE + chk], g_Wth + (size_t)row * IN_DIM + k0 + chk);
            }
        }
        asm volatile("cp.async.commit_group;");
    };

    float acc[2][6][4];
#pragma unroll
    for (int mi = 0; mi < 2; mi++)
#pragma unroll
        for (int ni = 0; ni < 6; ni++)
#pragma unroll
            for (int r = 0; r < 4; r++) acc[mi][ni][r] = 0.f;

    load_stage(0, 0);

    const int NIT = IN_DIM / 32;   // 8
    for (int it = 0; it < NIT; it++) {
        int buf = it & 1;
        if (it + 1 < NIT) {
            load_stage(buf ^ 1, (it + 1) * 32);
            asm volatile("cp.async.wait_group 1;");
        } else {
            asm volatile("cp.async.wait_group 0;");
        }
        __syncthreads();

        const __half* A = As[buf];
        const __half* B = Bs[buf];
#pragma unroll
        for (int ks = 0; ks < 2; ks++) {
            const int k16 = ks * 16;
            uint32_t ta[2][4], tb[6][2];
#pragma unroll
            for (int mi = 0; mi < 2; mi++) {
                int row = wm + mi * 16 + grp;
                ta[mi][0] = *reinterpret_cast<const uint32_t*>(&A[(row    ) * AS_STRIDE + k16 + 2 * tig    ]);
                ta[mi][1] = *reinterpret_cast<const uint32_t*>(&A[(row + 8) * AS_STRIDE + k16 + 2 * tig    ]);
                ta[mi][2] = *reinterpret_cast<const uint32_t*>(&A[(row    ) * AS_STRIDE + k16 + 2 * tig + 8]);
                ta[mi][3] = *reinterpret_cast<const uint32_t*>(&A[(row + 8) * AS_STRIDE + k16 + 2 * tig + 8]);
            }
#pragma unroll
            for (int ni = 0; ni < 6; ni++) {
                int col = wn + ni * 8 + grp;
                tb[ni][0] = *reinterpret_cast<const uint32_t*>(&B[col * AS_STRIDE + k16 + 2 * tig    ]);
                tb[ni][1] = *reinterpret_cast<const uint32_t*>(&B[col * AS_STRIDE + k16 + 2 * tig + 8]);
            }
#pragma unroll
            for (int mi = 0; mi < 2; mi++)
#pragma unroll
                for (int ni = 0; ni < 6; ni++) {
                    asm volatile(
                        "mma.sync.aligned.m16n8k16.row.col.f32.f16.f16.f32 "
                        "{%0,%1,%2,%3}, {%4,%5,%6,%7}, {%8,%9}, {%0,%1,%2,%3};"
                        : "+f"(acc[mi][ni][0]), "+f"(acc[mi][ni][1]),
                          "+f"(acc[mi][ni][2]), "+f"(acc[mi][ni][3])
                        : "r"(ta[mi][0]), "r"(ta[mi][1]), "r"(ta[mi][2]), "r"(ta[mi][3]),
                          "r"(tb[ni][0]), "r"(tb[ni][1]));
                }
        }
        __syncthreads();
    }

#pragma unroll
    for (int mi = 0; mi < 2; mi++) {
#pragma unroll
        for (int ni = 0; ni < 6; ni++) {
            int col = wn + ni * 8 + 2 * tig;
            float b0 = g_ball[col], b1 = g_ball[col + 1];
            int row = m0 + wm + mi * 16 + grp;
            if (row < M) {
                float2 o = make_float2(acc[mi][ni][0] + b0, acc[mi][ni][1] + b1);
                *reinterpret_cast<float2*>(g_hall + (size_t)row * HCOLS + col) = o;
                if (col < 128) g_hlp[(size_t)row * 64 + (col >> 1)] = __float22half2_rn(o);
            }
            if (row + 8 < M) {
                float2 o = make_float2(acc[mi][ni][2] + b0, acc[mi][ni][3] + b1);
                *reinterpret_cast<float2*>(g_hall + (size_t)(row + 8) * HCOLS + col) = o;
                if (col < 128) g_hlp[(size_t)(row + 8) * 64 + (col >> 1)] = __float22half2_rn(o);
            }
        }
    }
}

// ---------------- fused gather: TWO warps per node + epilogue ----------------
__global__ void __launch_bounds__(256) k_final(
    const float* __restrict__ wgh, const float* __restrict__ bgh,
    const float* __restrict__ wgl, const float* __restrict__ bgl,
    const float* __restrict__ wgi, const float* __restrict__ bgi,
    float* __restrict__ out, int n)
{
    __shared__ float sagg[4][2][128];
    int wid  = threadIdx.x >> 5;
    int pairid = wid >> 1;
    int half = wid & 1;
    int node = blockIdx.x * 4 + pairid;
    int lane = threadIdx.x & 31;

    if (node < n) {
        int beg = g_rowp[node], end = g_rowp[node + 1];
        int cnt = end - beg;
        int mid = beg + ((cnt + 1) >> 1);
        int w0 = half ? mid : beg;
        int w1 = half ? end : mid;

        float4 acc = make_float4(0.f, 0.f, 0.f, 0.f);
#define ROWLD(ss) *reinterpret_cast<const uint2*>(g_hlp + (size_t)(ss) * 64 + 2 * lane)
#define ACCUM(rr) { \
        float2 f0 = __half22float2(*reinterpret_cast<__half2*>(&rr.x)); \
        float2 f1 = __half22float2(*reinterpret_cast<__half2*>(&rr.y)); \
        acc.x += f0.x; acc.y += f0.y; acc.z += f1.x; acc.w += f1.y; }
        int p = w0;
        for (; p + 8 <= w1; p += 8) {
            int s0 = g_adj[p],     s1 = g_adj[p + 1], s2 = g_adj[p + 2], s3 = g_adj[p + 3];
            int s4 = g_adj[p + 4], s5 = g_adj[p + 5], s6 = g_adj[p + 6], s7 = g_adj[p + 7];
            uint2 r0 = ROWLD(s0), r1 = ROWLD(s1), r2 = ROWLD(s2), r3 = ROWLD(s3);
            uint2 r4 = ROWLD(s4), r5 = ROWLD(s5), r6 = ROWLD(s6), r7 = ROWLD(s7);
            ACCUM(r0) ACCUM(r1) ACCUM(r2) ACCUM(r3)
            ACCUM(r4) ACCUM(r5) ACCUM(r6) ACCUM(r7)
        }
        for (; p < w1; p++) {
            int src = g_adj[p];
            uint2 raw = ROWLD(src);
            ACCUM(raw)
        }
#undef ACCUM
#undef ROWLD
        *reinterpret_cast<float4*>(&sagg[pairid][half][lane * 4]) = acc;
    }
    __syncthreads();

    if (node >= n || half != 0) return;

    float isqd = g_isq[node];
    const float* hrow = g_hall + (size_t)node * HCOLS;
    float inv = g_inv[node];

    float Hhp[2], Hlp[2], Hi[2];
    float gh = 0.f, gl = 0.f, gi = 0.f;
#pragma unroll
    for (int t = 0; t < 2; t++) {
        int d = lane + t * 32;
        float hp = hrow[d], lp = hrow[64 + d], hi = hrow[128 + d];
        float ah = isqd * (sagg[pairid][0][d]      + sagg[pairid][1][d]);
        float al = isqd * (sagg[pairid][0][64 + d] + sagg[pairid][1][64 + d]);
        Hhp[t] = fmaxf(hp - (ah + inv * hp), 0.f);
        Hlp[t] = fmaxf(al + inv * lp, 0.f);
        Hi [t] = fmaxf(hi, 0.f);
        gh += Hhp[t] * wgh[d];
        gl += Hlp[t] * wgl[d];
        gi += Hi [t] * wgi[d];
    }
#pragma unroll
    for (int o = 16; o > 0; o >>= 1) {
        gh += __shfl_xor_sync(0xFFFFFFFFu, gh, o);
        gl += __shfl_xor_sync(0xFFFFFFFFu, gl, o);
        gi += __shfl_xor_sync(0xFFFFFFFFu, gi, o);
    }
    gh += bgh[0]; gl += bgl[0]; gi += bgi[0];

    float o0 = gh * Hhp[0] + gl * Hlp[0] + gi * Hi[0];
    float o1 = gh * Hhp[1] + gl * Hlp[1] + gi * Hi[1];

    float m = fmaxf(o0, o1);
#pragma unroll
    for (int o = 16; o > 0; o >>= 1) m = fmaxf(m, __shfl_xor_sync(0xFFFFFFFFu, m, o));
    float s = expf(o0 - m) + expf(o1 - m);
#pragma unroll
    for (int o = 16; o > 0; o >>= 1) s += __shfl_xor_sync(0xFFFFFFFFu, s, o);
    float lse = m + logf(s);

    out[(size_t)node * 64 + lane]      = o0 - lse;
    out[(size_t)node * 64 + lane + 32] = o1 - lse;
}

// ---------------- host launch ------------------------------------------------
extern "C" void kernel_launch(void* const* d_in, const int* in_sizes, int n_in,
                              void* d_out, int out_size) {
    const float* x  = (const float*)d_in[0];
    const void*  ei = d_in[1];
    const float* Whp = (const float*)d_in[2];
    const float* bhp = (const float*)d_in[3];
    const float* Wlp = (const float*)d_in[4];
    const float* blp = (const float*)d_in[5];
    const float* Wi  = (const float*)d_in[6];
    const float* bi  = (const float*)d_in[7];
    const float* wgh = (const float*)d_in[8];
    const float* bgh = (const float*)d_in[9];
    const float* wgl = (const float*)d_in[10];
    const float* bgl = (const float*)d_in[11];
    const float* wgi = (const float*)d_in[12];
    const float* bgi = (const float*)d_in[13];
    float* out = (float*)d_out;

    int n = in_sizes[0] / IN_DIM;   // 100000
    int E = in_sizes[1] / 2;        // 3200000
    int nb = (n + 1023) / 1024;

    static cudaStream_t s1 = nullptr;
    static cudaEvent_t ev_root = nullptr, ev_w = nullptr, ev_isq = nullptr, ev_side = nullptr;
    if (!s1) {   // first call = uncaptured correctness call: safe to create
        cudaFuncSetAttribute(k_gemm, cudaFuncAttributeMaxDynamicSharedMemorySize, GEMM_SMEM);
        cudaStreamCreateWithFlags(&s1, cudaStreamNonBlocking);
        cudaEventCreateWithFlags(&ev_root, cudaEventDisableTiming);
        cudaEventCreateWithFlags(&ev_w,    cudaEventDisableTiming);
        cudaEventCreateWithFlags(&ev_isq,  cudaEventDisableTiming);
        cudaEventCreateWithFlags(&ev_side, cudaEventDisableTiming);
    }

    cudaEventRecord(ev_root, 0);
    cudaStreamWaitEvent(s1, ev_root, 0);

    // launch order keeps k_gemm at global idx 3 (profiled slot).
    // stream 0: xh -> gemm;  s1: detect, prep_w (feeds gemm via ev_w), CSR chain.
    k_detect<<<1, 32, 0, s1>>>(ei, E, n);
    k_prep_w<<<(IN_DIM * HCOLS + 255) / 256, 256, 0, s1>>>(Whp, bhp, Wlp, blp, Wi, bi);
    k_xh<<<(n * IN_DIM / 4 + 255) / 256, 256>>>(x, n * IN_DIM / 4);
    cudaEventRecord(ev_w, s1);
    cudaStreamWaitEvent(0, ev_w, 0);
    k_gemm<<<(n + 127) / 128, 512, GEMM_SMEM>>>(n);      // idx 3
    // side stream: CSR prep
    k_zero<<<(n + 255) / 256, 256, 0, s1>>>(n);
    k_deg<<<(E + 255) / 256, 256, 0, s1>>>(ei, E, n);
    k_scan1<<<nb, 1024, 0, s1>>>(n);
    k_scan2<<<1, 128, 0, s1>>>(nb);
    k_scan3<<<(n + 255) / 256, 256, 0, s1>>>(n);
    cudaEventRecord(ev_isq, s1);
    k_scatter<<<(E + 255) / 256, 256, 0, s1>>>(ei, E, n);
    cudaEventRecord(ev_side, s1);

    cudaStreamWaitEvent(0, ev_isq, 0);
    k_prescale<<<(n * 32 + 255) / 256, 256>>>(n);

    cudaStreamWaitEvent(0, ev_side, 0);
    k_final<<<(n + 3) / 4, 256>>>(wgh, bgh, wgl, bgl, wgi, bgi, out, n);
}

// round 17
// speedup vs baseline: 1.0324x; 1.0324x over previous
#include <cuda_runtime.h>
#include <cuda_fp16.h>
#include <cstdint>

#define IN_DIM   256
#define OUT_DIM  64
#define HCOLS    192   // [hp | lp | i]
#define MAX_NODES 100000
#define MAX_EDGES 3300000

// ---------------- scratch (device globals: no allocations allowed) ----------
__device__ float   g_hall[(size_t)MAX_NODES * HCOLS];  // fp32 h (all paths)
__device__ __half2 g_hlp [(size_t)MAX_NODES * 64];     // fp16 mirror cols 0..127; pre-scaled by isq[src]
__device__ __half  g_xh  [(size_t)MAX_NODES * IN_DIM]; // fp16 mirror of x
__device__ __half  g_Wth [HCOLS * IN_DIM];             // fp16 W, TRANSPOSED: [n][k]
__device__ int     g_deg [MAX_NODES];
__device__ int     g_cur [MAX_NODES];
__device__ int     g_rowp[MAX_NODES + 1];
__device__ int     g_adj [MAX_EDGES];
__device__ float   g_isq [MAX_NODES];
__device__ float   g_inv [MAX_NODES];
__device__ float   g_ball[HCOLS];
__device__ int     g_is64;
__device__ int     g_bsum[128];

// ---------------- edge dtype detector (1 warp) -------------------------------
__global__ void k_detect(const void* __restrict__ ei, int E, int n) {
    const long long* p = (const long long*)ei;
    int lane = threadIdx.x;
    int idx = lane < E ? lane : (E > 0 ? E - 1 : 0);
    long long v = (E > 0) ? p[idx] : -1;
    bool good = (v >= 0 && v < (long long)n);
    unsigned all = __all_sync(0xFFFFFFFFu, good);
    if (lane == 0) g_is64 = all ? 1 : 0;
}

__device__ __forceinline__ int edge_at(const void* ei, size_t idx) {
    if (g_is64) return (int)((const long long*)ei)[idx];
    return ((const int*)ei)[idx];
}

// ---------------- x -> fp16 mirror -------------------------------------------
__global__ void k_xh(const float* __restrict__ x, int total4) {
    int t = blockIdx.x * blockDim.x + threadIdx.x;
    if (t >= total4) return;
    float4 v = reinterpret_cast<const float4*>(x)[t];
    __half2 h0 = __float22half2_rn(make_float2(v.x, v.y));
    __half2 h1 = __float22half2_rn(make_float2(v.z, v.w));
    uint2 o;
    o.x = *reinterpret_cast<uint32_t*>(&h0);
    o.y = *reinterpret_cast<uint32_t*>(&h1);
    reinterpret_cast<uint2*>(g_xh)[t] = o;
}

// ---------------- zero deg + cursors -----------------------------------------
__global__ void k_zero(int n) {
    int i = blockIdx.x * blockDim.x + threadIdx.x;
    if (i < n) { g_deg[i] = 0; g_cur[i] = 0; }
}

// ---------------- pack weights: fp16, transposed to [n][k] -------------------
__global__ void k_prep_w(const float* __restrict__ Whp, const float* __restrict__ bhp,
                         const float* __restrict__ Wlp, const float* __restrict__ blp,
                         const float* __restrict__ Wi,  const float* __restrict__ bi) {
    int idx = blockIdx.x * blockDim.x + threadIdx.x;
    if (idx < IN_DIM * HCOLS) {
        int k = idx / HCOLS, j = idx % HCOLS;
        float v;
        if      (j < 64)  v = Whp[k * 64 + j];
        else if (j < 128) v = Wlp[k * 64 + (j - 64)];
        else              v = Wi [k * 64 + (j - 128)];
        g_Wth[(size_t)j * IN_DIM + k] = __float2half_rn(v);
    }
    if (idx < HCOLS) {
        g_ball[idx] = (idx < 64) ? bhp[idx] : (idx < 128 ? blp[idx - 64] : bi[idx - 128]);
    }
}

// ---------------- degree count -----------------------------------------------
__global__ void k_deg(const void* __restrict__ ei, int E, int n) {
    int e = blockIdx.x * blockDim.x + threadIdx.x;
    if (e < E) {
        int dst = edge_at(ei, (size_t)E + e);
        if ((unsigned)dst < (unsigned)n) atomicAdd(&g_deg[dst], 1);
    }
}

// ---------------- multi-block scan: deg -> row_ptr ---------------------------
__global__ void __launch_bounds__(1024) k_scan1(int n) {
    __shared__ int sh[1024];
    int i = blockIdx.x * 1024 + threadIdx.x;
    sh[threadIdx.x] = (i < n) ? g_deg[i] : 0;
    __syncthreads();
#pragma unroll
    for (int off = 1; off < 1024; off <<= 1) {
        int t = (threadIdx.x >= off) ? sh[threadIdx.x - off] : 0;
        __syncthreads();
        sh[threadIdx.x] += t;
        __syncthreads();
    }
    if (i < n) g_rowp[i + 1] = sh[threadIdx.x];
    if (threadIdx.x == 1023) g_bsum[blockIdx.x] = sh[1023];
}
__global__ void __launch_bounds__(128) k_scan2(int nb) {
    __shared__ int sh[128];
    sh[threadIdx.x] = (threadIdx.x < nb) ? g_bsum[threadIdx.x] : 0;
    __syncthreads();
#pragma unroll
    for (int off = 1; off < 128; off <<= 1) {
        int t = (threadIdx.x >= off) ? sh[threadIdx.x - off] : 0;
        __syncthreads();
        sh[threadIdx.x] += t;
        __syncthreads();
    }
    g_bsum[threadIdx.x] = sh[threadIdx.x];
}
// scan3 + degfin fused
__global__ void k_scan3(int n) {
    int i = blockIdx.x * blockDim.x + threadIdx.x;
    if (i < n) {
        int b = i >> 10;
        if (b > 0) g_rowp[i + 1] += g_bsum[b - 1];
        float d = (float)g_deg[i] + 1.0f;
        g_isq[i] = rsqrtf(d);
        g_inv[i] = 1.0f / d;
    }
    if (i == 0) g_rowp[0] = 0;
}

// ---------------- scatter edges into CSR -------------------------------------
__global__ void k_scatter(const void* __restrict__ ei, int E, int n) {
    int e = blockIdx.x * blockDim.x + threadIdx.x;
    if (e < E) {
        int src = edge_at(ei, (size_t)e);
        int dst = edge_at(ei, (size_t)E + e);
        if ((unsigned)src < (unsigned)n && (unsigned)dst < (unsigned)n) {
            int pos = g_rowp[dst] + atomicAdd(&g_cur[dst], 1);
            if ((unsigned)pos < (unsigned)MAX_EDGES) g_adj[pos] = src;
        }
    }
}

// ---------------- prescale: g_hlp[i] *= isq[i] (row-wise) --------------------
__global__ void k_prescale(int n) {
    int t = blockIdx.x * blockDim.x + threadIdx.x;
    int total = n * 32;
    if (t >= total) return;
    int node = t >> 5;
    float s = g_isq[node];
    uint2 raw = *reinterpret_cast<const uint2*>(g_hlp + (size_t)t * 2);
    float2 f0 = __half22float2(*reinterpret_cast<__half2*>(&raw.x));
    float2 f1 = __half22float2(*reinterpret_cast<__half2*>(&raw.y));
    f0.x *= s; f0.y *= s; f1.x *= s; f1.y *= s;
    __half2 h0 = __float22half2_rn(f0), h1 = __float22half2_rn(f1);
    uint2 o; o.x = *reinterpret_cast<uint32_t*>(&h0); o.y = *reinterpret_cast<uint32_t*>(&h1);
    *reinterpret_cast<uint2*>(g_hlp + (size_t)t * 2) = o;
}

// ---------------- fp16 GEMM, cp.async double-buffered (R13-verified) ---------
__device__ __forceinline__ void cp16(void* smem, const void* gmem) {
    uint32_t s = (uint32_t)__cvta_generic_to_shared(smem);
    asm volatile("cp.async.cg.shared.global [%0], [%1], 16;" :: "r"(s), "l"(gmem));
}

#define AS_STRIDE 40
#define AS_ELEMS (128 * AS_STRIDE)
#define BS_ELEMS (HCOLS * AS_STRIDE)
#define GEMM_SMEM ((2 * AS_ELEMS + 2 * BS_ELEMS) * 2)   // 51200 bytes

__global__ void __launch_bounds__(512) k_gemm(int M) {
    extern __shared__ __half hsmem[];
    __half* As[2] = { hsmem, hsmem + AS_ELEMS };
    __half* Bs[2] = { hsmem + 2 * AS_ELEMS, hsmem + 2 * AS_ELEMS + BS_ELEMS };

    const int tid  = threadIdx.x;
    const int wid  = tid >> 5;
    const int lane = tid & 31;
    const int m0 = blockIdx.x * 128;
    const int wm = (wid >> 2) * 32;
    const int wn = (wid & 3) * 48;
    const int grp = lane >> 2;
    const int tig = lane & 3;

    const int arow = tid >> 2, achk = (tid & 3) * 8;
    auto load_stage = [&](int buf, int k0) {
        {
            int m = m0 + arow;
            int ms = m < M ? m : M - 1;
            cp16(&As[buf][arow * AS_STRIDE + achk], g_xh + (size_t)ms * IN_DIM + k0 + achk);
        }
#pragma unroll
        for (int r = 0; r < 2; r++) {
            int f = tid + r * 512;
            if (f < HCOLS * 4) {
                int row = f >> 2, chk = (f & 3) * 8;
                cp16(&Bs[buf][row * AS_STRIDE + chk], g_Wth + (size_t)row * IN_DIM + k0 + chk);
            }
        }
        asm volatile("cp.async.commit_group;");
    };

    float acc[2][6][4];
#pragma unroll
    for (int mi = 0; mi < 2; mi++)
#pragma unroll
        for (int ni = 0; ni < 6; ni++)
#pragma unroll
            for (int r = 0; r < 4; r++) acc[mi][ni][r] = 0.f;

    load_stage(0, 0);

    const int NIT = IN_DIM / 32;   // 8
    for (int it = 0; it < NIT; it++) {
        int buf = it & 1;
        if (it + 1 < NIT) {
            load_stage(buf ^ 1, (it + 1) * 32);
            asm volatile("cp.async.wait_group 1;");
        } else {
            asm volatile("cp.async.wait_group 0;");
        }
        __syncthreads();

        const __half* A = As[buf];
        const __half* B = Bs[buf];
#pragma unroll
        for (int ks = 0; ks < 2; ks++) {
            const int k16 = ks * 16;
            uint32_t ta[2][4], tb[6][2];
#pragma unroll
            for (int mi = 0; mi < 2; mi++) {
                int row = wm + mi * 16 + grp;
                ta[mi][0] = *reinterpret_cast<const uint32_t*>(&A[(row    ) * AS_STRIDE + k16 + 2 * tig    ]);
                ta[mi][1] = *reinterpret_cast<const uint32_t*>(&A[(row + 8) * AS_STRIDE + k16 + 2 * tig    ]);
                ta[mi][2] = *reinterpret_cast<const uint32_t*>(&A[(row    ) * AS_STRIDE + k16 + 2 * tig + 8]);
                ta[mi][3] = *reinterpret_cast<const uint32_t*>(&A[(row + 8) * AS_STRIDE + k16 + 2 * tig + 8]);
            }
#pragma unroll
            for (int ni = 0; ni < 6; ni++) {
                int col = wn + ni * 8 + grp;
                tb[ni][0] = *reinterpret_cast<const uint32_t*>(&B[col * AS_STRIDE + k16 + 2 * tig    ]);
                tb[ni][1] = *reinterpret_cast<const uint32_t*>(&B[col * AS_STRIDE + k16 + 2 * tig + 8]);
            }
#pragma unroll
            for (int mi = 0; mi < 2; mi++)
#pragma unroll
                for (int ni = 0; ni < 6; ni++) {
                    asm volatile(
                        "mma.sync.aligned.m16n8k16.row.col.f32.f16.f16.f32 "
                        "{%0,%1,%2,%3}, {%4,%5,%6,%7}, {%8,%9}, {%0,%1,%2,%3};"
                        : "+f"(acc[mi][ni][0]), "+f"(acc[mi][ni][1]),
                          "+f"(acc[mi][ni][2]), "+f"(acc[mi][ni][3])
                        : "r"(ta[mi][0]), "r"(ta[mi][1]), "r"(ta[mi][2]), "r"(ta[mi][3]),
                          "r"(tb[ni][0]), "r"(tb[ni][1]));
                }
        }
        __syncthreads();
    }

#pragma unroll
    for (int mi = 0; mi < 2; mi++) {
#pragma unroll
        for (int ni = 0; ni < 6; ni++) {
            int col = wn + ni * 8 + 2 * tig;
            float b0 = g_ball[col], b1 = g_ball[col + 1];
            int row = m0 + wm + mi * 16 + grp;
            if (row < M) {
                float2 o = make_float2(acc[mi][ni][0] + b0, acc[mi][ni][1] + b1);
                *reinterpret_cast<float2*>(g_hall + (size_t)row * HCOLS + col) = o;
                if (col < 128) g_hlp[(size_t)row * 64 + (col >> 1)] = __float22half2_rn(o);
            }
            if (row + 8 < M) {
                float2 o = make_float2(acc[mi][ni][2] + b0, acc[mi][ni][3] + b1);
                *reinterpret_cast<float2*>(g_hall + (size_t)(row + 8) * HCOLS + col) = o;
                if (col < 128) g_hlp[(size_t)(row + 8) * 64 + (col >> 1)] = __float22half2_rn(o);
            }
        }
    }
}

// ---------------- fused gather (R13-verified: warp/node, unroll-8) -----------
__global__ void __launch_bounds__(256) k_final(
    const float* __restrict__ wgh, const float* __restrict__ bgh,
    const float* __restrict__ wgl, const float* __restrict__ bgl,
    const float* __restrict__ wgi, const float* __restrict__ bgi,
    float* __restrict__ out, int n)
{
    __shared__ float sagg[8][128];
    int wslot = threadIdx.x >> 5;
    int node = blockIdx.x * 8 + wslot;
    int lane = threadIdx.x & 31;
    if (node >= n) return;

    int beg = g_rowp[node], end = g_rowp[node + 1];
    float isqd = g_isq[node];

    float4 acc = make_float4(0.f, 0.f, 0.f, 0.f);
#define ROWLD(ss) __ldg(reinterpret_cast<const uint2*>(g_hlp + (size_t)(ss) * 64 + 2 * lane))
#define ACCUM(rr) { \
        float2 f0 = __half22float2(*reinterpret_cast<__half2*>(&rr.x)); \
        float2 f1 = __half22float2(*reinterpret_cast<__half2*>(&rr.y)); \
        acc.x += f0.x; acc.y += f0.y; acc.z += f1.x; acc.w += f1.y; }
    int p = beg;
    for (; p + 8 <= end; p += 8) {
        int s0 = g_adj[p],     s1 = g_adj[p + 1], s2 = g_adj[p + 2], s3 = g_adj[p + 3];
        int s4 = g_adj[p + 4], s5 = g_adj[p + 5], s6 = g_adj[p + 6], s7 = g_adj[p + 7];
        uint2 r0 = ROWLD(s0), r1 = ROWLD(s1), r2 = ROWLD(s2), r3 = ROWLD(s3);
        uint2 r4 = ROWLD(s4), r5 = ROWLD(s5), r6 = ROWLD(s6), r7 = ROWLD(s7);
        ACCUM(r0) ACCUM(r1) ACCUM(r2) ACCUM(r3)
        ACCUM(r4) ACCUM(r5) ACCUM(r6) ACCUM(r7)
    }
    for (; p < end; p++) {
        int src = g_adj[p];
        uint2 raw = ROWLD(src);
        ACCUM(raw)
    }
#undef ACCUM
#undef ROWLD
    acc.x *= isqd; acc.y *= isqd; acc.z *= isqd; acc.w *= isqd;
    *reinterpret_cast<float4*>(&sagg[wslot][lane * 4]) = acc;
    __syncwarp();

    const float* hrow = g_hall + (size_t)node * HCOLS;
    const float* arow = sagg[wslot];
    float inv = g_inv[node];

    float Hhp[2], Hlp[2], Hi[2];
    float gh = 0.f, gl = 0.f, gi = 0.f;
#pragma unroll
    for (int t = 0; t < 2; t++) {
        int d = lane + t * 32;
        float hp = hrow[d], lp = hrow[64 + d], hi = hrow[128 + d];
        float ah = arow[d], al = arow[64 + d];
        Hhp[t] = fmaxf(hp - (ah + inv * hp), 0.f);
        Hlp[t] = fmaxf(al + inv * lp, 0.f);
        Hi [t] = fmaxf(hi, 0.f);
        gh += Hhp[t] * wgh[d];
        gl += Hlp[t] * wgl[d];
        gi += Hi [t] * wgi[d];
    }
#pragma unroll
    for (int o = 16; o > 0; o >>= 1) {
        gh += __shfl_xor_sync(0xFFFFFFFFu, gh, o);
        gl += __shfl_xor_sync(0xFFFFFFFFu, gl, o);
        gi += __shfl_xor_sync(0xFFFFFFFFu, gi, o);
    }
    gh += bgh[0]; gl += bgl[0]; gi += bgi[0];

    float o0 = gh * Hhp[0] + gl * Hlp[0] + gi * Hi[0];
    float o1 = gh * Hhp[1] + gl * Hlp[1] + gi * Hi[1];

    float m = fmaxf(o0, o1);
#pragma unroll
    for (int o = 16; o > 0; o >>= 1) m = fmaxf(m, __shfl_xor_sync(0xFFFFFFFFu, m, o));
    float s = expf(o0 - m) + expf(o1 - m);
#pragma unroll
    for (int o = 16; o > 0; o >>= 1) s += __shfl_xor_sync(0xFFFFFFFFu, s, o);
    float lse = m + logf(s);

    out[(size_t)node * 64 + lane]      = o0 - lse;
    out[(size_t)node * 64 + lane + 32] = o1 - lse;
}

// ---------------- host launch ------------------------------------------------
extern "C" void kernel_launch(void* const* d_in, const int* in_sizes, int n_in,
                              void* d_out, int out_size) {
    const float* x  = (const float*)d_in[0];
    const void*  ei = d_in[1];
    const float* Whp = (const float*)d_in[2];
    const float* bhp = (const float*)d_in[3];
    const float* Wlp = (const float*)d_in[4];
    const float* blp = (const float*)d_in[5];
    const float* Wi  = (const float*)d_in[6];
    const float* bi  = (const float*)d_in[7];
    const float* wgh = (const float*)d_in[8];
    const float* bgh = (const float*)d_in[9];
    const float* wgl = (const float*)d_in[10];
    const float* bgl = (const float*)d_in[11];
    const float* wgi = (const float*)d_in[12];
    const float* bgi = (const float*)d_in[13];
    float* out = (float*)d_out;

    int n = in_sizes[0] / IN_DIM;   // 100000
    int E = in_sizes[1] / 2;        // 3200000
    int nb = (n + 1023) / 1024;

    static cudaStream_t s1 = nullptr;
    static cudaEvent_t ev_root = nullptr, ev_w = nullptr, ev_isq = nullptr, ev_side = nullptr;
    if (!s1) {   // first call = uncaptured correctness call: safe to create
        cudaFuncSetAttribute(k_gemm, cudaFuncAttributeMaxDynamicSharedMemorySize, GEMM_SMEM);
        cudaStreamCreateWithFlags(&s1, cudaStreamNonBlocking);
        cudaEventCreateWithFlags(&ev_root, cudaEventDisableTiming);
        cudaEventCreateWithFlags(&ev_w,    cudaEventDisableTiming);
        cudaEventCreateWithFlags(&ev_isq,  cudaEventDisableTiming);
        cudaEventCreateWithFlags(&ev_side, cudaEventDisableTiming);
    }

    cudaEventRecord(ev_root, 0);
    cudaStreamWaitEvent(s1, ev_root, 0);

    // stream 0: xh -> gemm;  s1: detect, prep_w (feeds gemm via ev_w), CSR chain.
    // k_gemm stays at global launch idx 3 (profiled slot).
    k_detect<<<1, 32, 0, s1>>>(ei, E, n);
    k_prep_w<<<(IN_DIM * HCOLS + 255) / 256, 256, 0, s1>>>(Whp, bhp, Wlp, blp, Wi, bi);
    k_xh<<<(n * IN_DIM / 4 + 255) / 256, 256>>>(x, n * IN_DIM / 4);
    cudaEventRecord(ev_w, s1);
    cudaStreamWaitEvent(0, ev_w, 0);
    k_gemm<<<(n + 127) / 128, 512, GEMM_SMEM>>>(n);      // idx 3
    // side stream: CSR prep
    k_zero<<<(n + 255) / 256, 256, 0, s1>>>(n);
    k_deg<<<(E + 255) / 256, 256, 0, s1>>>(ei, E, n);
    k_scan1<<<nb, 1024, 0, s1>>>(n);
    k_scan2<<<1, 128, 0, s1>>>(nb);
    k_scan3<<<(n + 255) / 256, 256, 0, s1>>>(n);
    cudaEventRecord(ev_isq, s1);
    k_scatter<<<(E + 255) / 256, 256, 0, s1>>>(ei, E, n);
    cudaEventRecord(ev_side, s1);

    cudaStreamWaitEvent(0, ev_isq, 0);
    k_prescale<<<(n * 32 + 255) / 256, 256>>>(n);

    cudaStreamWaitEvent(0, ev_side, 0);
    k_final<<<(n + 7) / 8, 256>>>(wgh, bgh, wgl, bgl, wgi, bgi, out, n);
}